// round 1
// baseline (speedup 1.0000x reference)
#include <cuda_runtime.h>
#include <cstdint>

#define S 16
#define D 32
#define FFNH 64
#define WARPS 4
#define THREADS (WARPS * 32)

// ---- shared memory layout (float offsets) ----
#define OFF_WQ 0
#define OFF_WK 1024
#define OFF_WV 2048
#define OFF_WO 3072
#define OFF_W1 4096          // 32 x 64
#define OFF_W2 6144          // 64 x 32
#define OFF_BQ 8192
#define OFF_BK 8224
#define OFF_BV 8256
#define OFF_BO 8288
#define OFF_B1 8320          // 64
#define OFF_B2 8384          // 32
#define OFF_SCR 8416
#define SCR_PER_WARP 2560
#define SMEM_FLOATS (OFF_SCR + WARPS * SCR_PER_WARP)
#define SMEM_BYTES (SMEM_FLOATS * 4)

// per-warp scratch sub-offsets (floats). Regions are reused across phases:
//  SC_XT  [0,640)     : xT (32 rows x pad20)  -> later ctxT (same shape)
//  SC_Q   [640,1216)  : q  (16 rows x pad36)
//  SC_K   [1216,1792) : k  (16 rows x pad36)
//  SC_YT  [640,1280)  : yT (32 x pad20), written after q/k dead
//  SC_ATTN[1792,2112) : attn (16 x pad20)
//  SC_HT  [1280,2560) : hT (64 x pad20), written after k/attn dead
#define SC_XT   0
#define SC_Q    640
#define SC_K    1216
#define SC_YT   640
#define SC_ATTN 1792
#define SC_HT   1280

extern __shared__ float sm[];

__global__ __launch_bounds__(THREADS)
void tinyformer_kernel(
    const float* __restrict__ X,
    const float* __restrict__ Wq, const float* __restrict__ bq,
    const float* __restrict__ Wk, const float* __restrict__ bk,
    const float* __restrict__ Wv, const float* __restrict__ bv,
    const float* __restrict__ Wo, const float* __restrict__ bo,
    const float* __restrict__ W1, const float* __restrict__ b1,
    const float* __restrict__ W2, const float* __restrict__ b2,
    float* __restrict__ Out, int B)
{
    const int tid = threadIdx.x;

    // cooperative weight load into smem
    for (int i = tid; i < 1024; i += THREADS) {
        sm[OFF_WQ + i] = Wq[i];
        sm[OFF_WK + i] = Wk[i];
        sm[OFF_WV + i] = Wv[i];
        sm[OFF_WO + i] = Wo[i];
    }
    for (int i = tid; i < 2048; i += THREADS) {
        sm[OFF_W1 + i] = W1[i];
        sm[OFF_W2 + i] = W2[i];
    }
    if (tid < 32) {
        sm[OFF_BQ + tid] = bq[tid];
        sm[OFF_BK + tid] = bk[tid];
        sm[OFF_BV + tid] = bv[tid];
        sm[OFF_BO + tid] = bo[tid];
        sm[OFF_B2 + tid] = b2[tid];
    }
    if (tid < 64) sm[OFF_B1 + tid] = b1[tid];
    __syncthreads();

    const int lane = tid & 31;
    const int wid  = tid >> 5;
    float* scr = sm + OFF_SCR + wid * SCR_PER_WARP;

    const float bqv = sm[OFF_BQ + lane];
    const float bkv = sm[OFF_BK + lane];
    const float bvv = sm[OFF_BV + lane];
    const float bov = sm[OFF_BO + lane];
    const float b1a = sm[OFF_B1 + lane];
    const float b1b = sm[OFF_B1 + 32 + lane];
    const float b2v = sm[OFF_B2 + lane];

    const int gw = blockIdx.x * WARPS + wid;
    const int nw = gridDim.x * WARPS;

    for (int b = gw; b < B; b += nw) {
        const float* xb = X + (size_t)b * (S * D);

        // ---- load x tile; lane owns column `lane`; also store transposed xT[j][s]
        float xr[S];
        #pragma unroll
        for (int s = 0; s < S; s++) {
            xr[s] = xb[s * D + lane];
            scr[SC_XT + lane * 20 + s] = xr[s];
        }
        __syncwarp();

        // ---- fused Q,K,V projections: acc over j with xT broadcast rows
        float qa[S], ka[S], va[S];
        #pragma unroll
        for (int s = 0; s < S; s++) { qa[s] = bqv; ka[s] = bkv; va[s] = bvv; }
        #pragma unroll 4
        for (int j = 0; j < D; j++) {
            const float wq = sm[OFF_WQ + j * D + lane];
            const float wk = sm[OFF_WK + j * D + lane];
            const float wv = sm[OFF_WV + j * D + lane];
            const float4* xrow = (const float4*)&scr[SC_XT + j * 20];
            #pragma unroll
            for (int s4 = 0; s4 < 4; s4++) {
                float4 xv = xrow[s4];
                float xs[4] = {xv.x, xv.y, xv.z, xv.w};
                #pragma unroll
                for (int u = 0; u < 4; u++) {
                    qa[4 * s4 + u] = fmaf(xs[u], wq, qa[4 * s4 + u]);
                    ka[4 * s4 + u] = fmaf(xs[u], wk, ka[4 * s4 + u]);
                    va[4 * s4 + u] = fmaf(xs[u], wv, va[4 * s4 + u]);
                }
            }
        }
        // stage q,k to smem ([s][d], pad 36); v stays in registers
        #pragma unroll
        for (int s = 0; s < S; s++) {
            scr[SC_Q + s * 36 + lane] = qa[s];
            scr[SC_K + s * 36 + lane] = ka[s];
        }
        __syncwarp();

        // ---- scores + softmax. Pair p = lane + 32*i: s = p>>4, t = p&15.
        const float scl = 0.17677669529663687f;  // 1/sqrt(32)
        const int shalf = lane >> 4;
        const int tt = lane & 15;
        #pragma unroll 2
        for (int i = 0; i < 8; i++) {
            const int srow = 2 * i + shalf;
            const float4* qrow = (const float4*)&scr[SC_Q + srow * 36];
            const float4* krow = (const float4*)&scr[SC_K + tt * 36];
            float acc = 0.f;
            #pragma unroll
            for (int d4 = 0; d4 < 8; d4++) {
                float4 qv = qrow[d4];
                float4 kv = krow[d4];
                acc += qv.x * kv.x + qv.y * kv.y + qv.z * kv.z + qv.w * kv.w;
            }
            acc *= scl;
            // softmax across the 16-lane t-group (xor <= 8 stays in-group)
            float m = acc;
            #pragma unroll
            for (int off = 8; off; off >>= 1)
                m = fmaxf(m, __shfl_xor_sync(0xffffffffu, m, off));
            const float e = __expf(acc - m);
            float ssum = e;
            #pragma unroll
            for (int off = 8; off; off >>= 1)
                ssum += __shfl_xor_sync(0xffffffffu, ssum, off);
            scr[SC_ATTN + srow * 20 + tt] = e * (1.0f / ssum);
        }
        __syncwarp();

        // ---- context = attn @ v (v register-resident), store transposed ctxT
        #pragma unroll 4
        for (int s = 0; s < S; s++) {
            const float4* arow = (const float4*)&scr[SC_ATTN + s * 20];
            float acc = 0.f;
            #pragma unroll
            for (int t4 = 0; t4 < 4; t4++) {
                float4 a = arow[t4];
                acc += a.x * va[4 * t4 + 0] + a.y * va[4 * t4 + 1]
                     + a.z * va[4 * t4 + 2] + a.w * va[4 * t4 + 3];
            }
            scr[SC_XT + lane * 20 + s] = acc;  // ctxT[lane][s] reuses xT region
        }
        __syncwarp();

        // ---- O projection + residual 1
        float ya[S];
        #pragma unroll
        for (int s = 0; s < S; s++) ya[s] = bov;
        #pragma unroll 4
        for (int j = 0; j < D; j++) {
            const float wo = sm[OFF_WO + j * D + lane];
            const float4* crow = (const float4*)&scr[SC_XT + j * 20];
            #pragma unroll
            for (int s4 = 0; s4 < 4; s4++) {
                float4 c = crow[s4];
                float cs[4] = {c.x, c.y, c.z, c.w};
                #pragma unroll
                for (int u = 0; u < 4; u++)
                    ya[4 * s4 + u] = fmaf(cs[u], wo, ya[4 * s4 + u]);
            }
        }
        #pragma unroll
        for (int s = 0; s < S; s++) ya[s] += xr[s];
        // store yT (reuses q/k region — both dead)
        #pragma unroll
        for (int s = 0; s < S; s++) scr[SC_YT + lane * 20 + s] = ya[s];
        __syncwarp();

        // ---- FFN layer 1 (+ReLU): lane owns f=lane and f=lane+32
        float ha[S], hb[S];
        #pragma unroll
        for (int s = 0; s < S; s++) { ha[s] = b1a; hb[s] = b1b; }
        #pragma unroll 4
        for (int j = 0; j < D; j++) {
            const float w1a = sm[OFF_W1 + j * FFNH + lane];
            const float w1b = sm[OFF_W1 + j * FFNH + 32 + lane];
            const float4* yrow = (const float4*)&scr[SC_YT + j * 20];
            #pragma unroll
            for (int s4 = 0; s4 < 4; s4++) {
                float4 yv = yrow[s4];
                float ys[4] = {yv.x, yv.y, yv.z, yv.w};
                #pragma unroll
                for (int u = 0; u < 4; u++) {
                    ha[4 * s4 + u] = fmaf(ys[u], w1a, ha[4 * s4 + u]);
                    hb[4 * s4 + u] = fmaf(ys[u], w1b, hb[4 * s4 + u]);
                }
            }
        }
        #pragma unroll
        for (int s = 0; s < S; s++) {
            scr[SC_HT + lane * 20 + s]        = fmaxf(ha[s], 0.f);
            scr[SC_HT + (32 + lane) * 20 + s] = fmaxf(hb[s], 0.f);
        }
        __syncwarp();

        // ---- FFN layer 2 + residual 2 -> global
        float za[S];
        #pragma unroll
        for (int s = 0; s < S; s++) za[s] = b2v;
        #pragma unroll 4
        for (int f = 0; f < FFNH; f++) {
            const float w2 = sm[OFF_W2 + f * D + lane];
            const float4* hrow = (const float4*)&scr[SC_HT + f * 20];
            #pragma unroll
            for (int s4 = 0; s4 < 4; s4++) {
                float4 h = hrow[s4];
                float hs[4] = {h.x, h.y, h.z, h.w};
                #pragma unroll
                for (int u = 0; u < 4; u++)
                    za[4 * s4 + u] = fmaf(hs[u], w2, za[4 * s4 + u]);
            }
        }
        float* ob = Out + (size_t)b * (S * D);
        #pragma unroll
        for (int s = 0; s < S; s++) ob[s * D + lane] = za[s] + ya[s];
        __syncwarp();  // order this iter's smem reads before next iter's writes
    }
}

extern "C" void kernel_launch(void* const* d_in, const int* in_sizes, int n_in,
                              void* d_out, int out_size) {
    const float* X  = (const float*)d_in[0];
    const float* Wq = (const float*)d_in[1];
    const float* bq = (const float*)d_in[2];
    const float* Wk = (const float*)d_in[3];
    const float* bk = (const float*)d_in[4];
    const float* Wv = (const float*)d_in[5];
    const float* bv = (const float*)d_in[6];
    const float* Wo = (const float*)d_in[7];
    const float* bo = (const float*)d_in[8];
    const float* W1 = (const float*)d_in[9];
    const float* b1 = (const float*)d_in[10];
    const float* W2 = (const float*)d_in[11];
    const float* b2 = (const float*)d_in[12];
    float* Out = (float*)d_out;

    const int B = in_sizes[0] / (S * D);

    cudaFuncSetAttribute(tinyformer_kernel,
                         cudaFuncAttributeMaxDynamicSharedMemorySize, SMEM_BYTES);

    // 148 SMs x 3 blocks (smem-limited occupancy) = one full wave
    int blocks = 444;
    int max_blocks = (B + WARPS - 1) / WARPS;
    if (blocks > max_blocks) blocks = max_blocks;

    tinyformer_kernel<<<blocks, THREADS, SMEM_BYTES>>>(
        X, Wq, bq, Wk, bk, Wv, bv, Wo, bo, W1, b1, W2, b2, Out, B);
}

// round 2
// speedup vs baseline: 1.3325x; 1.3325x over previous
#include <cuda_runtime.h>
#include <cstdint>

#define S 16
#define D 32
#define FFNH 64
#define WARPS 16
#define THREADS (WARPS * 32)

// ---- shared memory layout (float offsets) ----
#define OFF_WQ 0
#define OFF_WK 1024
#define OFF_WV 2048
#define OFF_WO 3072
#define OFF_W1 4096          // 32 x 64
#define OFF_W2 6144          // 64 x 32
#define OFF_BQ 8192
#define OFF_BK 8224
#define OFF_BV 8256
#define OFF_BO 8288
#define OFF_B1 8320          // 64
#define OFF_B2 8384          // 32
#define OFF_SCR 8416
#define SCR_PER_WARP 2560
#define SMEM_FLOATS (OFF_SCR + WARPS * SCR_PER_WARP)
#define SMEM_BYTES (SMEM_FLOATS * 4)

// per-warp scratch (float offsets within warp region), rows padded to 20 floats
//  SC_XT [0,640)     xT (32x20)  -> later ctxT
//  SC_QT [640,1280)  qT (32x20)  -> later yT
//  SC_KT [1280,1920) kT (32x20)  -> later hT[0:32]
//  SC_AT [1920,2240) attnT(16x20)-> later hT[32:64] region tail
//  SC_HT [1280,2560) hT (64x20)
#define SC_XT 0
#define SC_QT 640
#define SC_KT 1280
#define SC_AT 1920
#define SC_HT 1280

extern __shared__ float sm[];

// ---------- packed f32x2 helpers (Blackwell) ----------
__device__ __forceinline__ uint64_t pk2(float a, float b) {
    uint64_t r;
    asm("mov.b64 %0, {%1, %2};" : "=l"(r) : "r"(__float_as_uint(a)), "r"(__float_as_uint(b)));
    return r;
}
__device__ __forceinline__ uint64_t dup2(float a) { return pk2(a, a); }
__device__ __forceinline__ void upk2(uint64_t p, float& a, float& b) {
    uint32_t u0, u1;
    asm("mov.b64 {%0, %1}, %2;" : "=r"(u0), "=r"(u1) : "l"(p));
    a = __uint_as_float(u0); b = __uint_as_float(u1);
}
__device__ __forceinline__ uint64_t fma2(uint64_t a, uint64_t b, uint64_t c) {
    uint64_t d;
    asm("fma.rn.f32x2 %0, %1, %2, %3;" : "=l"(d) : "l"(a), "l"(b), "l"(c));
    return d;
}
__device__ __forceinline__ uint64_t add2(uint64_t a, uint64_t b) {
    uint64_t d;
    asm("add.rn.f32x2 %0, %1, %2;" : "=l"(d) : "l"(a), "l"(b));
    return d;
}
__device__ __forceinline__ uint64_t mul2(uint64_t a, uint64_t b) {
    uint64_t d;
    asm("mul.rn.f32x2 %0, %1, %2;" : "=l"(d) : "l"(a), "l"(b));
    return d;
}
// 128-bit shared load as two packed pairs
__device__ __forceinline__ void lds128p(uint64_t& a, uint64_t& b, uint32_t addr) {
    asm volatile("ld.shared.v2.b64 {%0, %1}, [%2];" : "=l"(a), "=l"(b) : "r"(addr));
}
// 128-bit shared store from two packed pairs
__device__ __forceinline__ void sts128p(uint32_t addr, uint64_t a, uint64_t b) {
    asm volatile("st.shared.v2.b64 [%0], {%1, %2};" :: "r"(addr), "l"(a), "l"(b));
}
__device__ __forceinline__ float ldsf(uint32_t addr) {
    float v;
    asm volatile("ld.shared.f32 %0, [%1];" : "=f"(v) : "r"(addr));
    return v;
}

__global__ __launch_bounds__(THREADS, 1)
void tinyformer_kernel(
    const float* __restrict__ X,
    const float* __restrict__ Wq, const float* __restrict__ bq,
    const float* __restrict__ Wk, const float* __restrict__ bk,
    const float* __restrict__ Wv, const float* __restrict__ bv,
    const float* __restrict__ Wo, const float* __restrict__ bo,
    const float* __restrict__ W1, const float* __restrict__ b1,
    const float* __restrict__ W2, const float* __restrict__ b2,
    float* __restrict__ Out, int B)
{
    const int tid = threadIdx.x;

    // cooperative weight load into smem
    for (int i = tid; i < 1024; i += THREADS) {
        sm[OFF_WQ + i] = Wq[i];
        sm[OFF_WK + i] = Wk[i];
        sm[OFF_WV + i] = Wv[i];
        sm[OFF_WO + i] = Wo[i];
    }
    for (int i = tid; i < 2048; i += THREADS) {
        sm[OFF_W1 + i] = W1[i];
        sm[OFF_W2 + i] = W2[i];
    }
    if (tid < 32) {
        sm[OFF_BQ + tid] = bq[tid];
        sm[OFF_BK + tid] = bk[tid];
        sm[OFF_BV + tid] = bv[tid];
        sm[OFF_BO + tid] = bo[tid];
        sm[OFF_B2 + tid] = b2[tid];
    }
    if (tid < 64) sm[OFF_B1 + tid] = b1[tid];
    __syncthreads();

    const int lane = tid & 31;
    const int wid  = tid >> 5;

    const uint32_t smb  = (uint32_t)__cvta_generic_to_shared(sm);
    const uint32_t scrb = smb + (OFF_SCR + wid * SCR_PER_WARP) * 4u;

    // broadcast-duplicated bias pairs (hoisted out of batch loop)
    const uint64_t bq2  = dup2(sm[OFF_BQ + lane]);
    const uint64_t bk2  = dup2(sm[OFF_BK + lane]);
    const uint64_t bv2  = dup2(sm[OFF_BV + lane]);
    const uint64_t bo2  = dup2(sm[OFF_BO + lane]);
    const uint64_t b1a2 = dup2(sm[OFF_B1 + lane]);
    const uint64_t b1b2 = dup2(sm[OFF_B1 + 32 + lane]);
    const uint64_t b22  = dup2(sm[OFF_B2 + lane]);
    const uint64_t scl2 = dup2(0.17677669529663687f);   // 1/sqrt(32)

    const int gw = blockIdx.x * WARPS + wid;
    const int nw = gridDim.x * WARPS;

    const int tt    = lane & 15;
    const int shalf = lane >> 4;

    for (int b = gw; b < B; b += nw) {
        const float* xb = X + (size_t)b * (S * D);

        // ---- load x; lane owns column `lane`. Pack s-pairs; write xT row `lane`.
        uint64_t xp[8];
        {
            float xr[S];
            #pragma unroll
            for (int s = 0; s < S; s++) xr[s] = xb[s * D + lane];
            #pragma unroll
            for (int p = 0; p < 8; p++) xp[p] = pk2(xr[2 * p], xr[2 * p + 1]);
            const uint32_t xrow = scrb + (SC_XT + lane * 20) * 4u;
            #pragma unroll
            for (int c = 0; c < 4; c++)
                sts128p(xrow + c * 16u, xp[2 * c], xp[2 * c + 1]);
        }
        __syncwarp();

        // ---- fused Q,K,V projections (pairs over s)
        uint64_t qa[8], ka[8], va[8];
        #pragma unroll
        for (int p = 0; p < 8; p++) { qa[p] = bq2; ka[p] = bk2; va[p] = bv2; }
        #pragma unroll 4
        for (int j = 0; j < D; j++) {
            const uint64_t wq2 = dup2(sm[OFF_WQ + j * D + lane]);
            const uint64_t wk2 = dup2(sm[OFF_WK + j * D + lane]);
            const uint64_t wv2 = dup2(sm[OFF_WV + j * D + lane]);
            const uint32_t xr  = scrb + (SC_XT + j * 20) * 4u;
            uint64_t x2[8];
            #pragma unroll
            for (int c = 0; c < 4; c++) lds128p(x2[2 * c], x2[2 * c + 1], xr + c * 16u);
            #pragma unroll
            for (int p = 0; p < 8; p++) {
                qa[p] = fma2(x2[p], wq2, qa[p]);
                ka[p] = fma2(x2[p], wk2, ka[p]);
                va[p] = fma2(x2[p], wv2, va[p]);
            }
        }
        // pre-scale q by 1/sqrt(D)
        #pragma unroll
        for (int p = 0; p < 8; p++) qa[p] = mul2(qa[p], scl2);
        // stage qT,kT rows (feature-major: row = feature `lane`, cols = tokens)
        {
            const uint32_t qrow = scrb + (SC_QT + lane * 20) * 4u;
            const uint32_t krow = scrb + (SC_KT + lane * 20) * 4u;
            #pragma unroll
            for (int c = 0; c < 4; c++) {
                sts128p(qrow + c * 16u, qa[2 * c], qa[2 * c + 1]);
                sts128p(krow + c * 16u, ka[2 * c], ka[2 * c + 1]);
            }
        }
        __syncwarp();

        // ---- scores: lane computes scores[s][tt] for s in [8*shalf, 8*shalf+8)
        uint64_t sc[4];
        #pragma unroll
        for (int p = 0; p < 4; p++) sc[p] = 0ull;
        #pragma unroll 4
        for (int d = 0; d < D; d++) {
            const uint32_t base = scrb + (SC_QT + d * 20 + 8 * shalf) * 4u;
            const uint64_t k2 = dup2(ldsf(scrb + (SC_KT + d * 20 + tt) * 4u));
            uint64_t q2[4];
            lds128p(q2[0], q2[1], base);
            lds128p(q2[2], q2[3], base + 16u);
            #pragma unroll
            for (int p = 0; p < 4; p++) sc[p] = fma2(q2[p], k2, sc[p]);
        }
        // softmax over t (16-lane xor group)
        {
            float s_[8];
            #pragma unroll
            for (int p = 0; p < 4; p++) upk2(sc[p], s_[2 * p], s_[2 * p + 1]);
            float a_[8];
            #pragma unroll
            for (int i = 0; i < 8; i++) {
                float m = s_[i];
                #pragma unroll
                for (int off = 8; off; off >>= 1)
                    m = fmaxf(m, __shfl_xor_sync(0xffffffffu, m, off));
                const float e = __expf(s_[i] - m);
                float ssum = e;
                #pragma unroll
                for (int off = 8; off; off >>= 1)
                    ssum += __shfl_xor_sync(0xffffffffu, ssum, off);
                a_[i] = __fdividef(e, ssum);
            }
            // store attnT[t][s]: lane writes row tt, cols 8*shalf..+7
            const uint32_t arow = scrb + (SC_AT + tt * 20 + 8 * shalf) * 4u;
            sts128p(arow,       pk2(a_[0], a_[1]), pk2(a_[2], a_[3]));
            sts128p(arow + 16u, pk2(a_[4], a_[5]), pk2(a_[6], a_[7]));
        }
        __syncwarp();

        // ---- context = attn @ v  (v register-resident, pairs over s)
        float vs[S];
        #pragma unroll
        for (int p = 0; p < 8; p++) upk2(va[p], vs[2 * p], vs[2 * p + 1]);
        uint64_t cx[8];
        #pragma unroll
        for (int p = 0; p < 8; p++) cx[p] = 0ull;
        #pragma unroll 4
        for (int t = 0; t < S; t++) {
            const uint64_t v2 = dup2(vs[t]);
            const uint32_t ar = scrb + (SC_AT + t * 20) * 4u;
            uint64_t a2[8];
            #pragma unroll
            for (int c = 0; c < 4; c++) lds128p(a2[2 * c], a2[2 * c + 1], ar + c * 16u);
            #pragma unroll
            for (int p = 0; p < 8; p++) cx[p] = fma2(a2[p], v2, cx[p]);
        }
        // stage ctxT rows (reuse xT region)
        {
            const uint32_t crow = scrb + (SC_XT + lane * 20) * 4u;
            #pragma unroll
            for (int c = 0; c < 4; c++)
                sts128p(crow + c * 16u, cx[2 * c], cx[2 * c + 1]);
        }
        __syncwarp();

        // ---- O projection + residual 1
        uint64_t ya[8];
        #pragma unroll
        for (int p = 0; p < 8; p++) ya[p] = bo2;
        #pragma unroll 4
        for (int j = 0; j < D; j++) {
            const uint64_t wo2 = dup2(sm[OFF_WO + j * D + lane]);
            const uint32_t cr  = scrb + (SC_XT + j * 20) * 4u;
            uint64_t c2[8];
            #pragma unroll
            for (int c = 0; c < 4; c++) lds128p(c2[2 * c], c2[2 * c + 1], cr + c * 16u);
            #pragma unroll
            for (int p = 0; p < 8; p++) ya[p] = fma2(c2[p], wo2, ya[p]);
        }
        #pragma unroll
        for (int p = 0; p < 8; p++) ya[p] = add2(ya[p], xp[p]);
        // stage yT rows (reuse qT region)
        {
            const uint32_t yrow = scrb + (SC_QT + lane * 20) * 4u;
            #pragma unroll
            for (int c = 0; c < 4; c++)
                sts128p(yrow + c * 16u, ya[2 * c], ya[2 * c + 1]);
        }
        __syncwarp();

        // ---- FFN layer 1 (+ReLU): lane owns features lane and lane+32
        uint64_t ha[8], hb[8];
        #pragma unroll
        for (int p = 0; p < 8; p++) { ha[p] = b1a2; hb[p] = b1b2; }
        #pragma unroll 4
        for (int j = 0; j < D; j++) {
            const uint64_t w1a2 = dup2(sm[OFF_W1 + j * FFNH + lane]);
            const uint64_t w1b2 = dup2(sm[OFF_W1 + j * FFNH + 32 + lane]);
            const uint32_t yr   = scrb + (SC_QT + j * 20) * 4u;
            uint64_t y2[8];
            #pragma unroll
            for (int c = 0; c < 4; c++) lds128p(y2[2 * c], y2[2 * c + 1], yr + c * 16u);
            #pragma unroll
            for (int p = 0; p < 8; p++) {
                ha[p] = fma2(y2[p], w1a2, ha[p]);
                hb[p] = fma2(y2[p], w1b2, hb[p]);
            }
        }
        // ReLU + stage hT rows lane and lane+32 (reuse kT/attnT region)
        {
            const uint32_t hrow0 = scrb + (SC_HT + lane * 20) * 4u;
            const uint32_t hrow1 = scrb + (SC_HT + (32 + lane) * 20) * 4u;
            #pragma unroll
            for (int c = 0; c < 4; c++) {
                float a0, a1, a2v, a3;
                upk2(ha[2 * c], a0, a1); upk2(ha[2 * c + 1], a2v, a3);
                sts128p(hrow0 + c * 16u,
                        pk2(fmaxf(a0, 0.f), fmaxf(a1, 0.f)),
                        pk2(fmaxf(a2v, 0.f), fmaxf(a3, 0.f)));
                upk2(hb[2 * c], a0, a1); upk2(hb[2 * c + 1], a2v, a3);
                sts128p(hrow1 + c * 16u,
                        pk2(fmaxf(a0, 0.f), fmaxf(a1, 0.f)),
                        pk2(fmaxf(a2v, 0.f), fmaxf(a3, 0.f)));
            }
        }
        __syncwarp();

        // ---- FFN layer 2 + residual 2 -> global
        uint64_t za[8];
        #pragma unroll
        for (int p = 0; p < 8; p++) za[p] = b22;
        #pragma unroll 4
        for (int f = 0; f < FFNH; f++) {
            const uint64_t w22 = dup2(sm[OFF_W2 + f * D + lane]);
            const uint32_t hr  = scrb + (SC_HT + f * 20) * 4u;
            uint64_t h2[8];
            #pragma unroll
            for (int c = 0; c < 4; c++) lds128p(h2[2 * c], h2[2 * c + 1], hr + c * 16u);
            #pragma unroll
            for (int p = 0; p < 8; p++) za[p] = fma2(h2[p], w22, za[p]);
        }
        float* ob = Out + (size_t)b * (S * D);
        #pragma unroll
        for (int p = 0; p < 8; p++) {
            const uint64_t z2 = add2(za[p], ya[p]);
            float z0, z1;
            upk2(z2, z0, z1);
            ob[(2 * p) * D + lane]     = z0;
            ob[(2 * p + 1) * D + lane] = z1;
        }
        __syncwarp();  // order this iter's smem reads before next iter's writes
    }
}

extern "C" void kernel_launch(void* const* d_in, const int* in_sizes, int n_in,
                              void* d_out, int out_size) {
    const float* X  = (const float*)d_in[0];
    const float* Wq = (const float*)d_in[1];
    const float* bq = (const float*)d_in[2];
    const float* Wk = (const float*)d_in[3];
    const float* bk = (const float*)d_in[4];
    const float* Wv = (const float*)d_in[5];
    const float* bv = (const float*)d_in[6];
    const float* Wo = (const float*)d_in[7];
    const float* bo = (const float*)d_in[8];
    const float* W1 = (const float*)d_in[9];
    const float* b1 = (const float*)d_in[10];
    const float* W2 = (const float*)d_in[11];
    const float* b2 = (const float*)d_in[12];
    float* Out = (float*)d_out;

    const int B = in_sizes[0] / (S * D);

    cudaFuncSetAttribute(tinyformer_kernel,
                         cudaFuncAttributeMaxDynamicSharedMemorySize, SMEM_BYTES);

    // one 16-warp block per SM (smem-limited), persistent batch loop
    int blocks = 148;
    int max_blocks = (B + WARPS - 1) / WARPS;
    if (blocks > max_blocks) blocks = max_blocks;

    tinyformer_kernel<<<blocks, THREADS, SMEM_BYTES>>>(
        X, Wq, bq, Wk, bk, Wv, bv, Wo, bo, W1, b1, W2, b2, Out, B);
}

// round 5
// speedup vs baseline: 1.4642x; 1.0988x over previous
#include <cuda_runtime.h>
#include <cstdint>

#define S 16
#define D 32
#define FFNH 64
#define WARPS 16
#define THREADS 512

// ---- smem float offsets ----
#define W_QSW 0
#define W_KSW 1024
#define W_VSW 2048
#define W_OSW 3072
#define W_1A  4096
#define W_1B  5120
#define W_2SW 6144
#define B_Q   8192
#define B_K   8224
#define B_V   8256
#define B_O   8288
#define B_1   8320
#define B_2   8384
#define OFF_SCR 8416
#define SCR_FL 2560
#define SMEM_FLOATS (OFF_SCR + WARPS * SCR_FL)
#define SMEM_BYTES (SMEM_FLOATS * 4)

// warp-scratch regions (float offsets), rows padded to 20 (vsw: 36)
//  R_XT [0,640)    xT (32x20)           live: load -> O residual
//  R_QT [640,1280) qT (32x20)           live: QKV -> scores; then attnT; then yT
//  R_KT [1280,1920) kT (32x20)          live: QKV -> scores; then ctxT; then hT lo
//  R_VS [1920,2496) vsw (16x36)         live: QKV -> ctx;    then hT hi
#define R_XT 0
#define R_QT 640
#define R_KT 1280
#define R_VS 1920
#define R_AT 640
#define R_CT 1280
#define R_YT 640
#define R_HT 1280

extern __shared__ float sm[];

// ---------- packed f32x2 helpers ----------
__device__ __forceinline__ uint64_t pk2(float a, float b) {
    uint64_t r;
    asm("mov.b64 %0, {%1, %2};" : "=l"(r) : "r"(__float_as_uint(a)), "r"(__float_as_uint(b)));
    return r;
}
__device__ __forceinline__ uint64_t dup2(float a) { return pk2(a, a); }
__device__ __forceinline__ void upk2(uint64_t p, float& a, float& b) {
    uint32_t u0, u1;
    asm("mov.b64 {%0, %1}, %2;" : "=r"(u0), "=r"(u1) : "l"(p));
    a = __uint_as_float(u0); b = __uint_as_float(u1);
}
__device__ __forceinline__ uint64_t fma2(uint64_t a, uint64_t b, uint64_t c) {
    uint64_t d;
    asm("fma.rn.f32x2 %0, %1, %2, %3;" : "=l"(d) : "l"(a), "l"(b), "l"(c));
    return d;
}
__device__ __forceinline__ uint64_t add2(uint64_t a, uint64_t b) {
    uint64_t d;
    asm("add.rn.f32x2 %0, %1, %2;" : "=l"(d) : "l"(a), "l"(b));
    return d;
}
__device__ __forceinline__ uint64_t mul2(uint64_t a, uint64_t b) {
    uint64_t d;
    asm("mul.rn.f32x2 %0, %1, %2;" : "=l"(d) : "l"(a), "l"(b));
    return d;
}
__device__ __forceinline__ void lds128p(uint64_t& a, uint64_t& b, uint32_t addr) {
    asm volatile("ld.shared.v2.b64 {%0, %1}, [%2];" : "=l"(a), "=l"(b) : "r"(addr));
}
__device__ __forceinline__ void sts128p(uint32_t addr, uint64_t a, uint64_t b) {
    asm volatile("st.shared.v2.b64 [%0], {%1, %2};" :: "r"(addr), "l"(a), "l"(b));
}
__device__ __forceinline__ float ldsf(uint32_t addr) {
    float v;
    asm volatile("ld.shared.f32 %0, [%1];" : "=f"(v) : "r"(addr));
    return v;
}
__device__ __forceinline__ void lds128f(float4& v, uint32_t addr) {
    asm volatile("ld.shared.v4.f32 {%0,%1,%2,%3}, [%4];"
                 : "=f"(v.x), "=f"(v.y), "=f"(v.z), "=f"(v.w) : "r"(addr));
}
__device__ __forceinline__ float frcp(float x) {
    float r;
    asm("rcp.approx.f32 %0, %1;" : "=f"(r) : "f"(x));
    return r;
}
__device__ __forceinline__ uint64_t shfl_add2(uint64_t v, int mask) {
    uint64_t o = __shfl_xor_sync(0xffffffffu, (unsigned long long)v, mask);
    return add2(v, o);
}

__global__ __launch_bounds__(THREADS, 1)
void tinyformer_kernel(
    const float* __restrict__ X,
    const float* __restrict__ Wq, const float* __restrict__ bq,
    const float* __restrict__ Wk, const float* __restrict__ bk,
    const float* __restrict__ Wv, const float* __restrict__ bv,
    const float* __restrict__ Wo, const float* __restrict__ bo,
    const float* __restrict__ W1, const float* __restrict__ b1,
    const float* __restrict__ W2, const float* __restrict__ b2,
    float* __restrict__ Out, int B)
{
    const int tid = threadIdx.x;

    // ---- build swizzled weights: w_sw[j][og*4+m] = W[j][og+8m] ----
    for (int i = tid; i < 1024; i += THREADS) {
        const int j = i >> 5, c = i & 31, ogb = c >> 2, mb = c & 3;
        const int src = j * 32 + ogb + 8 * mb;
        sm[W_QSW + i] = Wq[src];
        sm[W_KSW + i] = Wk[src];
        sm[W_VSW + i] = Wv[src];
        sm[W_OSW + i] = Wo[src];
        sm[W_1A + i]  = W1[j * 64 + ogb + 8 * mb];        // f = og+8m       (0..31)
        sm[W_1B + i]  = W1[j * 64 + 32 + ogb + 8 * mb];   // f = 32+og+8m    (32..63)
    }
    for (int i = tid; i < 2048; i += THREADS) {
        const int f = i >> 5, c = i & 31, ogb = c >> 2, mb = c & 3;
        sm[W_2SW + i] = W2[f * 32 + ogb + 8 * mb];
    }
    if (tid < 32) {
        sm[B_Q + tid] = bq[tid];
        sm[B_K + tid] = bk[tid];
        sm[B_V + tid] = bv[tid];
        sm[B_O + tid] = bo[tid];
        sm[B_2 + tid] = b2[tid];
    }
    if (tid < 64) sm[B_1 + tid] = b1[tid];
    __syncthreads();

    const int lane = tid & 31;
    const int wid  = tid >> 5;
    const int sg   = lane >> 3;   // s-quad: s in [4sg, 4sg+4)
    const int og   = lane & 7;    // feature group: o = og + 8m

    const uint32_t smb  = (uint32_t)__cvta_generic_to_shared(sm);
    const uint32_t scrb = smb + (OFF_SCR + wid * SCR_FL) * 4u;
    const uint32_t a_xt = scrb + R_XT * 4u;
    const uint32_t a_qt = scrb + R_QT * 4u;
    const uint32_t a_kt = scrb + R_KT * 4u;
    const uint32_t a_vs = scrb + R_VS * 4u;
    const uint32_t a_at = scrb + R_AT * 4u;
    const uint32_t a_ct = scrb + R_CT * 4u;
    const uint32_t a_yt = scrb + R_YT * 4u;
    const uint32_t a_ht = scrb + R_HT * 4u;
    const uint32_t w_q  = smb + W_QSW * 4u;
    const uint32_t w_k  = smb + W_KSW * 4u;
    const uint32_t w_v  = smb + W_VSW * 4u;
    const uint32_t w_o  = smb + W_OSW * 4u;
    const uint32_t w_1a = smb + W_1A * 4u;
    const uint32_t w_1b = smb + W_1B * 4u;
    const uint32_t w_2  = smb + W_2SW * 4u;

    const uint64_t scl2 = dup2(0.17677669529663687f);   // 1/sqrt(32)

    // per-lane biases (one-time loads, kept in regs)
    uint64_t bqd[4], bkd[4], bvd[4], bod[4], b2d[4], b1d[8];
    #pragma unroll
    for (int m = 0; m < 4; m++) {
        bqd[m] = dup2(sm[B_Q + og + 8 * m]);
        bkd[m] = dup2(sm[B_K + og + 8 * m]);
        bvd[m] = dup2(sm[B_V + og + 8 * m]);
        bod[m] = dup2(sm[B_O + og + 8 * m]);
        b2d[m] = dup2(sm[B_2 + og + 8 * m]);
    }
    #pragma unroll
    for (int m = 0; m < 8; m++) b1d[m] = dup2(sm[B_1 + og + 8 * m]);

    const int gw = blockIdx.x * WARPS + wid;
    const int nw = gridDim.x * WARPS;

    for (int b = gw; b < B; b += nw) {
        const float* xb = X + (size_t)b * (S * D);

        // ===== phase 1: load x (lane owns column `lane`), store xT rows =====
        {
            float xr[S];
            #pragma unroll
            for (int s = 0; s < S; s++) xr[s] = xb[s * D + lane];
            const uint32_t xrow = a_xt + lane * 80u;   // 20 floats * 4B
            #pragma unroll
            for (int c = 0; c < 4; c++)
                sts128p(xrow + c * 16u,
                        pk2(xr[4 * c], xr[4 * c + 1]),
                        pk2(xr[4 * c + 2], xr[4 * c + 3]));
        }
        __syncwarp();   // S1

        // ===== phase 2: fused QKV (tile: lane owns 4s x 4o per matrix) =====
        uint64_t qa[4][2], ka[4][2], va[4][2];
        #pragma unroll
        for (int m = 0; m < 4; m++) {
            qa[m][0] = bqd[m]; qa[m][1] = bqd[m];
            ka[m][0] = bkd[m]; ka[m][1] = bkd[m];
            va[m][0] = bvd[m]; va[m][1] = bvd[m];
        }
        #pragma unroll 4
        for (int j = 0; j < D; j++) {
            uint64_t x0, x1;
            lds128p(x0, x1, a_xt + j * 80u + sg * 16u);
            float4 wq4, wk4, wv4;
            lds128f(wq4, w_q + j * 128u + og * 16u);
            lds128f(wk4, w_k + j * 128u + og * 16u);
            lds128f(wv4, w_v + j * 128u + og * 16u);
            const float* q4 = (const float*)&wq4;
            const float* k4 = (const float*)&wk4;
            const float* v4 = (const float*)&wv4;
            #pragma unroll
            for (int m = 0; m < 4; m++) {
                const uint64_t wq2 = dup2(q4[m]), wk2 = dup2(k4[m]), wv2 = dup2(v4[m]);
                qa[m][0] = fma2(x0, wq2, qa[m][0]); qa[m][1] = fma2(x1, wq2, qa[m][1]);
                ka[m][0] = fma2(x0, wk2, ka[m][0]); ka[m][1] = fma2(x1, wk2, ka[m][1]);
                va[m][0] = fma2(x0, wv2, va[m][0]); va[m][1] = fma2(x1, wv2, va[m][1]);
            }
        }
        // scale q by 1/sqrt(D); stage qT, kT (feature-major rows)
        #pragma unroll
        for (int m = 0; m < 4; m++) {
            qa[m][0] = mul2(qa[m][0], scl2);
            qa[m][1] = mul2(qa[m][1], scl2);
            const uint32_t off = (og + 8 * m) * 80u + sg * 16u;
            sts128p(a_qt + off, qa[m][0], qa[m][1]);
            sts128p(a_kt + off, ka[m][0], ka[m][1]);
        }
        // stage v swizzled token-major: vsw[t][og*4+m] = v[t][og+8m]
        {
            float vf[4][4];   // [m][token i]
            #pragma unroll
            for (int m = 0; m < 4; m++) {
                upk2(va[m][0], vf[m][0], vf[m][1]);
                upk2(va[m][1], vf[m][2], vf[m][3]);
            }
            #pragma unroll
            for (int i = 0; i < 4; i++)
                sts128p(a_vs + ((4 * sg + i) * 36u + og * 4u) * 4u,
                        pk2(vf[0][i], vf[1][i]), pk2(vf[2][i], vf[3][i]));
        }
        __syncwarp();   // S2

        // ===== phase 3: scores (lane owns 4s x {t=og, t=og+8}) =====
        uint64_t sc[2][2] = {{0ull, 0ull}, {0ull, 0ull}};
        #pragma unroll 4
        for (int d = 0; d < D; d++) {
            uint64_t q0, q1;
            lds128p(q0, q1, a_qt + d * 80u + sg * 16u);
            const uint64_t k0 = dup2(ldsf(a_kt + (d * 20 + og) * 4u));
            const uint64_t k1 = dup2(ldsf(a_kt + (d * 20 + og + 8) * 4u));
            sc[0][0] = fma2(q0, k0, sc[0][0]); sc[0][1] = fma2(q1, k0, sc[0][1]);
            sc[1][0] = fma2(q0, k1, sc[1][0]); sc[1][1] = fma2(q1, k1, sc[1][1]);
        }
        __syncwarp();   // S3: all qT/kT reads done before attnT overwrites R_QT

        // ===== phase 4: softmax over t (no max-sub: |score| small) =====
        {
            float e[2][4];
            #pragma unroll
            for (int n = 0; n < 2; n++) {
                float f0, f1;
                upk2(sc[n][0], f0, f1);
                e[n][0] = __expf(f0); e[n][1] = __expf(f1);
                upk2(sc[n][1], f0, f1);
                e[n][2] = __expf(f0); e[n][3] = __expf(f1);
            }
            uint64_t ps0 = pk2(e[0][0] + e[1][0], e[0][1] + e[1][1]);
            uint64_t ps1 = pk2(e[0][2] + e[1][2], e[0][3] + e[1][3]);
            ps0 = shfl_add2(ps0, 1); ps1 = shfl_add2(ps1, 1);
            ps0 = shfl_add2(ps0, 2); ps1 = shfl_add2(ps1, 2);
            ps0 = shfl_add2(ps0, 4); ps1 = shfl_add2(ps1, 4);
            float s0, s1, s2, s3;
            upk2(ps0, s0, s1); upk2(ps1, s2, s3);
            const uint64_t rs0 = pk2(frcp(s0), frcp(s1));
            const uint64_t rs1 = pk2(frcp(s2), frcp(s3));
            #pragma unroll
            for (int n = 0; n < 2; n++) {
                const uint64_t a0 = mul2(pk2(e[n][0], e[n][1]), rs0);
                const uint64_t a1 = mul2(pk2(e[n][2], e[n][3]), rs1);
                sts128p(a_at + ((og + 8 * n) * 20u + sg * 4u) * 4u, a0, a1);
            }
        }
        __syncwarp();   // S4

        // ===== phase 5: context = attn @ v (lane owns 4s x 4d) =====
        uint64_t cx[4][2];
        #pragma unroll
        for (int m = 0; m < 4; m++) { cx[m][0] = 0ull; cx[m][1] = 0ull; }
        #pragma unroll 4
        for (int t = 0; t < S; t++) {
            uint64_t a0, a1;
            lds128p(a0, a1, a_at + t * 80u + sg * 16u);
            float4 v4;
            lds128f(v4, a_vs + (t * 36u + og * 4u) * 4u);
            const float* vv = (const float*)&v4;
            #pragma unroll
            for (int m = 0; m < 4; m++) {
                const uint64_t v2 = dup2(vv[m]);
                cx[m][0] = fma2(a0, v2, cx[m][0]);
                cx[m][1] = fma2(a1, v2, cx[m][1]);
            }
        }
        #pragma unroll
        for (int m = 0; m < 4; m++)
            sts128p(a_ct + ((og + 8 * m) * 20u + sg * 4u) * 4u, cx[m][0], cx[m][1]);
        __syncwarp();   // S5

        // ===== phase 6: O projection + residual 1 =====
        uint64_t ya[4][2];
        #pragma unroll
        for (int m = 0; m < 4; m++) { ya[m][0] = bod[m]; ya[m][1] = bod[m]; }
        #pragma unroll 4
        for (int j = 0; j < D; j++) {
            uint64_t c0, c1;
            lds128p(c0, c1, a_ct + j * 80u + sg * 16u);
            float4 wo4;
            lds128f(wo4, w_o + j * 128u + og * 16u);
            const float* o4 = (const float*)&wo4;
            #pragma unroll
            for (int m = 0; m < 4; m++) {
                const uint64_t w2v = dup2(o4[m]);
                ya[m][0] = fma2(c0, w2v, ya[m][0]);
                ya[m][1] = fma2(c1, w2v, ya[m][1]);
            }
        }
        // residual: x tile re-read from xT
        #pragma unroll
        for (int m = 0; m < 4; m++) {
            uint64_t x0, x1;
            lds128p(x0, x1, a_xt + ((og + 8 * m) * 20u + sg * 4u) * 4u);
            ya[m][0] = add2(ya[m][0], x0);
            ya[m][1] = add2(ya[m][1], x1);
        }
        #pragma unroll
        for (int m = 0; m < 4; m++)
            sts128p(a_yt + ((og + 8 * m) * 20u + sg * 4u) * 4u, ya[m][0], ya[m][1]);
        __syncwarp();   // S6

        // ===== phase 7: FFN1 + ReLU (lane owns 4s x 8f) =====
        uint64_t ha[8][2];
        #pragma unroll
        for (int m = 0; m < 8; m++) { ha[m][0] = b1d[m]; ha[m][1] = b1d[m]; }
        #pragma unroll 4
        for (int j = 0; j < D; j++) {
            uint64_t y0, y1;
            lds128p(y0, y1, a_yt + j * 80u + sg * 16u);
            float4 wa4, wb4;
            lds128f(wa4, w_1a + j * 128u + og * 16u);
            lds128f(wb4, w_1b + j * 128u + og * 16u);
            const float* wa = (const float*)&wa4;
            const float* wb = (const float*)&wb4;
            #pragma unroll
            for (int m = 0; m < 4; m++) {
                const uint64_t w2a = dup2(wa[m]), w2b = dup2(wb[m]);
                ha[m][0]     = fma2(y0, w2a, ha[m][0]);
                ha[m][1]     = fma2(y1, w2a, ha[m][1]);
                ha[m + 4][0] = fma2(y0, w2b, ha[m + 4][0]);
                ha[m + 4][1] = fma2(y1, w2b, ha[m + 4][1]);
            }
        }
        #pragma unroll
        for (int m = 0; m < 8; m++) {
            float f0, f1, f2, f3;
            upk2(ha[m][0], f0, f1);
            upk2(ha[m][1], f2, f3);
            sts128p(a_ht + ((og + 8 * m) * 20u + sg * 4u) * 4u,
                    pk2(fmaxf(f0, 0.f), fmaxf(f1, 0.f)),
                    pk2(fmaxf(f2, 0.f), fmaxf(f3, 0.f)));
        }
        __syncwarp();   // S7

        // ===== phase 8: FFN2 + residual 2 -> global =====
        uint64_t za[4][2];
        #pragma unroll
        for (int m = 0; m < 4; m++) { za[m][0] = b2d[m]; za[m][1] = b2d[m]; }
        #pragma unroll 4
        for (int f = 0; f < FFNH; f++) {
            uint64_t h0, h1;
            lds128p(h0, h1, a_ht + f * 80u + sg * 16u);
            float4 w24;
            lds128f(w24, w_2 + f * 128u + og * 16u);
            const float* w4 = (const float*)&w24;
            #pragma unroll
            for (int m = 0; m < 4; m++) {
                const uint64_t w2v = dup2(w4[m]);
                za[m][0] = fma2(h0, w2v, za[m][0]);
                za[m][1] = fma2(h1, w2v, za[m][1]);
            }
        }
        float* ob = Out + (size_t)b * (S * D);
        #pragma unroll
        for (int m = 0; m < 4; m++) {
            #pragma unroll
            for (int p = 0; p < 2; p++) {
                const uint64_t z2 = add2(za[m][p], ya[m][p]);
                float z0, z1;
                upk2(z2, z0, z1);
                const int s0 = 4 * sg + 2 * p;
                ob[s0 * D + og + 8 * m]       = z0;
                ob[(s0 + 1) * D + og + 8 * m] = z1;
            }
        }
        __syncwarp();   // order hT reads before next batch's stores
    }
}

extern "C" void kernel_launch(void* const* d_in, const int* in_sizes, int n_in,
                              void* d_out, int out_size) {
    const float* X  = (const float*)d_in[0];
    const float* Wq = (const float*)d_in[1];
    const float* bq = (const float*)d_in[2];
    const float* Wk = (const float*)d_in[3];
    const float* bk = (const float*)d_in[4];
    const float* Wv = (const float*)d_in[5];
    const float* bv = (const float*)d_in[6];
    const float* Wo = (const float*)d_in[7];
    const float* bo = (const float*)d_in[8];
    const float* W1 = (const float*)d_in[9];
    const float* b1 = (const float*)d_in[10];
    const float* W2 = (const float*)d_in[11];
    const float* b2 = (const float*)d_in[12];
    float* Out = (float*)d_out;

    const int B = in_sizes[0] / (S * D);

    cudaFuncSetAttribute(tinyformer_kernel,
                         cudaFuncAttributeMaxDynamicSharedMemorySize, SMEM_BYTES);

    int blocks = 148;
    int max_blocks = (B + WARPS - 1) / WARPS;
    if (blocks > max_blocks) blocks = max_blocks;

    tinyformer_kernel<<<blocks, THREADS, SMEM_BYTES>>>(
        X, Wq, bq, Wk, bk, Wv, bv, Wo, bo, W1, b1, W2, b2, Out, B);
}

// round 6
// speedup vs baseline: 1.4666x; 1.0017x over previous
#include <cuda_runtime.h>
#include <cstdint>

#define S 16
#define D 32
#define FFNH 64
#define WARPS 16
#define THREADS 512

// ---- smem float offsets ----
#define W_QSW 0
#define W_KSW 1024
#define W_VSW 2048
#define W_OSW 3072
#define W_1A  4096
#define W_1B  5120
#define W_2SW 6144
#define B_Q   8192
#define B_K   8224
#define B_V   8256
#define B_O   8288
#define B_1   8320
#define B_2   8384
#define OFF_SCR 8416
#define SCR_FL 2560
#define SMEM_FLOATS (OFF_SCR + WARPS * SCR_FL)
#define SMEM_BYTES (SMEM_FLOATS * 4)

// warp-scratch regions (float offsets), rows padded to 20 (vsw: 36)
//  R_XT [0,640)    xT (32x20)           live: load -> O residual
//  R_QT [640,1280) qT (32x20)           live: QKV -> scores; then attnT; then yT
//  R_KT [1280,1920) kT (32x20)          live: QKV -> scores; then ctxT; then hT lo
//  R_VS [1920,2496) vsw (16x36)         live: QKV -> ctx;    then hT hi
#define R_XT 0
#define R_QT 640
#define R_KT 1280
#define R_VS 1920
#define R_AT 640
#define R_CT 1280
#define R_YT 640
#define R_HT 1280

extern __shared__ float sm[];

// ---------- packed f32x2 helpers ----------
__device__ __forceinline__ uint64_t pk2(float a, float b) {
    uint64_t r;
    asm("mov.b64 %0, {%1, %2};" : "=l"(r) : "r"(__float_as_uint(a)), "r"(__float_as_uint(b)));
    return r;
}
__device__ __forceinline__ uint64_t dup2(float a) { return pk2(a, a); }
__device__ __forceinline__ void upk2(uint64_t p, float& a, float& b) {
    uint32_t u0, u1;
    asm("mov.b64 {%0, %1}, %2;" : "=r"(u0), "=r"(u1) : "l"(p));
    a = __uint_as_float(u0); b = __uint_as_float(u1);
}
__device__ __forceinline__ uint64_t fma2(uint64_t a, uint64_t b, uint64_t c) {
    uint64_t d;
    asm("fma.rn.f32x2 %0, %1, %2, %3;" : "=l"(d) : "l"(a), "l"(b), "l"(c));
    return d;
}
__device__ __forceinline__ uint64_t add2(uint64_t a, uint64_t b) {
    uint64_t d;
    asm("add.rn.f32x2 %0, %1, %2;" : "=l"(d) : "l"(a), "l"(b));
    return d;
}
__device__ __forceinline__ uint64_t mul2(uint64_t a, uint64_t b) {
    uint64_t d;
    asm("mul.rn.f32x2 %0, %1, %2;" : "=l"(d) : "l"(a), "l"(b));
    return d;
}
__device__ __forceinline__ void lds128p(uint64_t& a, uint64_t& b, uint32_t addr) {
    asm volatile("ld.shared.v2.b64 {%0, %1}, [%2];" : "=l"(a), "=l"(b) : "r"(addr));
}
__device__ __forceinline__ void sts128p(uint32_t addr, uint64_t a, uint64_t b) {
    asm volatile("st.shared.v2.b64 [%0], {%1, %2};" :: "r"(addr), "l"(a), "l"(b));
}
__device__ __forceinline__ float ldsf(uint32_t addr) {
    float v;
    asm volatile("ld.shared.f32 %0, [%1];" : "=f"(v) : "r"(addr));
    return v;
}
__device__ __forceinline__ void lds128f(float4& v, uint32_t addr) {
    asm volatile("ld.shared.v4.f32 {%0,%1,%2,%3}, [%4];"
                 : "=f"(v.x), "=f"(v.y), "=f"(v.z), "=f"(v.w) : "r"(addr));
}
__device__ __forceinline__ float frcp(float x) {
    float r;
    asm("rcp.approx.f32 %0, %1;" : "=f"(r) : "f"(x));
    return r;
}
__device__ __forceinline__ uint64_t shfl_add2(uint64_t v, int mask) {
    uint64_t o = __shfl_xor_sync(0xffffffffu, (unsigned long long)v, mask);
    return add2(v, o);
}

__global__ __launch_bounds__(THREADS, 1)
void tinyformer_kernel(
    const float* __restrict__ X,
    const float* __restrict__ Wq, const float* __restrict__ bq,
    const float* __restrict__ Wk, const float* __restrict__ bk,
    const float* __restrict__ Wv, const float* __restrict__ bv,
    const float* __restrict__ Wo, const float* __restrict__ bo,
    const float* __restrict__ W1, const float* __restrict__ b1,
    const float* __restrict__ W2, const float* __restrict__ b2,
    float* __restrict__ Out, int B)
{
    const int tid = threadIdx.x;

    // ---- build swizzled weights: w_sw[j][og*4+m] = W[j][og+8m] ----
    for (int i = tid; i < 1024; i += THREADS) {
        const int j = i >> 5, c = i & 31, ogb = c >> 2, mb = c & 3;
        const int src = j * 32 + ogb + 8 * mb;
        sm[W_QSW + i] = Wq[src];
        sm[W_KSW + i] = Wk[src];
        sm[W_VSW + i] = Wv[src];
        sm[W_OSW + i] = Wo[src];
        sm[W_1A + i]  = W1[j * 64 + ogb + 8 * mb];        // f = og+8m       (0..31)
        sm[W_1B + i]  = W1[j * 64 + 32 + ogb + 8 * mb];   // f = 32+og+8m    (32..63)
    }
    for (int i = tid; i < 2048; i += THREADS) {
        const int f = i >> 5, c = i & 31, ogb = c >> 2, mb = c & 3;
        sm[W_2SW + i] = W2[f * 32 + ogb + 8 * mb];
    }
    if (tid < 32) {
        sm[B_Q + tid] = bq[tid];
        sm[B_K + tid] = bk[tid];
        sm[B_V + tid] = bv[tid];
        sm[B_O + tid] = bo[tid];
        sm[B_2 + tid] = b2[tid];
    }
    if (tid < 64) sm[B_1 + tid] = b1[tid];
    __syncthreads();

    const int lane = tid & 31;
    const int wid  = tid >> 5;
    const int sg   = lane >> 3;   // s-quad: s in [4sg, 4sg+4)
    const int og   = lane & 7;    // feature group: o = og + 8m

    const uint32_t smb  = (uint32_t)__cvta_generic_to_shared(sm);
    const uint32_t scrb = smb + (OFF_SCR + wid * SCR_FL) * 4u;
    const uint32_t a_xt = scrb + R_XT * 4u;
    const uint32_t a_qt = scrb + R_QT * 4u;
    const uint32_t a_kt = scrb + R_KT * 4u;
    const uint32_t a_vs = scrb + R_VS * 4u;
    const uint32_t a_at = scrb + R_AT * 4u;
    const uint32_t a_ct = scrb + R_CT * 4u;
    const uint32_t a_yt = scrb + R_YT * 4u;
    const uint32_t a_ht = scrb + R_HT * 4u;
    const uint32_t w_q  = smb + W_QSW * 4u;
    const uint32_t w_k  = smb + W_KSW * 4u;
    const uint32_t w_v  = smb + W_VSW * 4u;
    const uint32_t w_o  = smb + W_OSW * 4u;
    const uint32_t w_1a = smb + W_1A * 4u;
    const uint32_t w_1b = smb + W_1B * 4u;
    const uint32_t w_2  = smb + W_2SW * 4u;

    const uint64_t scl2 = dup2(0.17677669529663687f);   // 1/sqrt(32)

    // per-lane biases (one-time loads, kept in regs)
    uint64_t bqd[4], bkd[4], bvd[4], bod[4], b2d[4], b1d[8];
    #pragma unroll
    for (int m = 0; m < 4; m++) {
        bqd[m] = dup2(sm[B_Q + og + 8 * m]);
        bkd[m] = dup2(sm[B_K + og + 8 * m]);
        bvd[m] = dup2(sm[B_V + og + 8 * m]);
        bod[m] = dup2(sm[B_O + og + 8 * m]);
        b2d[m] = dup2(sm[B_2 + og + 8 * m]);
    }
    #pragma unroll
    for (int m = 0; m < 8; m++) b1d[m] = dup2(sm[B_1 + og + 8 * m]);

    const int gw = blockIdx.x * WARPS + wid;
    const int nw = gridDim.x * WARPS;

    for (int b = gw; b < B; b += nw) {
        const float* xb = X + (size_t)b * (S * D);

        // ===== phase 1: load x (lane owns column `lane`), store xT rows =====
        {
            float xr[S];
            #pragma unroll
            for (int s = 0; s < S; s++) xr[s] = xb[s * D + lane];
            const uint32_t xrow = a_xt + lane * 80u;   // 20 floats * 4B
            #pragma unroll
            for (int c = 0; c < 4; c++)
                sts128p(xrow + c * 16u,
                        pk2(xr[4 * c], xr[4 * c + 1]),
                        pk2(xr[4 * c + 2], xr[4 * c + 3]));
        }
        __syncwarp();   // S1

        // ===== phase 2: fused QKV (tile: lane owns 4s x 4o per matrix) =====
        uint64_t qa[4][2], ka[4][2], va[4][2];
        #pragma unroll
        for (int m = 0; m < 4; m++) {
            qa[m][0] = bqd[m]; qa[m][1] = bqd[m];
            ka[m][0] = bkd[m]; ka[m][1] = bkd[m];
            va[m][0] = bvd[m]; va[m][1] = bvd[m];
        }
        #pragma unroll 4
        for (int j = 0; j < D; j++) {
            uint64_t x0, x1;
            lds128p(x0, x1, a_xt + j * 80u + sg * 16u);
            float4 wq4, wk4, wv4;
            lds128f(wq4, w_q + j * 128u + og * 16u);
            lds128f(wk4, w_k + j * 128u + og * 16u);
            lds128f(wv4, w_v + j * 128u + og * 16u);
            const float* q4 = (const float*)&wq4;
            const float* k4 = (const float*)&wk4;
            const float* v4 = (const float*)&wv4;
            #pragma unroll
            for (int m = 0; m < 4; m++) {
                const uint64_t wq2 = dup2(q4[m]), wk2 = dup2(k4[m]), wv2 = dup2(v4[m]);
                qa[m][0] = fma2(x0, wq2, qa[m][0]); qa[m][1] = fma2(x1, wq2, qa[m][1]);
                ka[m][0] = fma2(x0, wk2, ka[m][0]); ka[m][1] = fma2(x1, wk2, ka[m][1]);
                va[m][0] = fma2(x0, wv2, va[m][0]); va[m][1] = fma2(x1, wv2, va[m][1]);
            }
        }
        // scale q by 1/sqrt(D); stage qT, kT (feature-major rows)
        #pragma unroll
        for (int m = 0; m < 4; m++) {
            qa[m][0] = mul2(qa[m][0], scl2);
            qa[m][1] = mul2(qa[m][1], scl2);
            const uint32_t off = (og + 8 * m) * 80u + sg * 16u;
            sts128p(a_qt + off, qa[m][0], qa[m][1]);
            sts128p(a_kt + off, ka[m][0], ka[m][1]);
        }
        // stage v swizzled token-major: vsw[t][og*4+m] = v[t][og+8m]
        {
            float vf[4][4];   // [m][token i]
            #pragma unroll
            for (int m = 0; m < 4; m++) {
                upk2(va[m][0], vf[m][0], vf[m][1]);
                upk2(va[m][1], vf[m][2], vf[m][3]);
            }
            #pragma unroll
            for (int i = 0; i < 4; i++)
                sts128p(a_vs + ((4 * sg + i) * 36u + og * 4u) * 4u,
                        pk2(vf[0][i], vf[1][i]), pk2(vf[2][i], vf[3][i]));
        }
        __syncwarp();   // S2

        // ===== phase 3: scores (lane owns 4s x {t=og, t=og+8}) =====
        uint64_t sc[2][2] = {{0ull, 0ull}, {0ull, 0ull}};
        #pragma unroll 4
        for (int d = 0; d < D; d++) {
            uint64_t q0, q1;
            lds128p(q0, q1, a_qt + d * 80u + sg * 16u);
            const uint64_t k0 = dup2(ldsf(a_kt + (d * 20 + og) * 4u));
            const uint64_t k1 = dup2(ldsf(a_kt + (d * 20 + og + 8) * 4u));
            sc[0][0] = fma2(q0, k0, sc[0][0]); sc[0][1] = fma2(q1, k0, sc[0][1]);
            sc[1][0] = fma2(q0, k1, sc[1][0]); sc[1][1] = fma2(q1, k1, sc[1][1]);
        }
        __syncwarp();   // S3: all qT/kT reads done before attnT overwrites R_QT

        // ===== phase 4: softmax over t (no max-sub: |score| small) =====
        {
            float e[2][4];
            #pragma unroll
            for (int n = 0; n < 2; n++) {
                float f0, f1;
                upk2(sc[n][0], f0, f1);
                e[n][0] = __expf(f0); e[n][1] = __expf(f1);
                upk2(sc[n][1], f0, f1);
                e[n][2] = __expf(f0); e[n][3] = __expf(f1);
            }
            uint64_t ps0 = pk2(e[0][0] + e[1][0], e[0][1] + e[1][1]);
            uint64_t ps1 = pk2(e[0][2] + e[1][2], e[0][3] + e[1][3]);
            ps0 = shfl_add2(ps0, 1); ps1 = shfl_add2(ps1, 1);
            ps0 = shfl_add2(ps0, 2); ps1 = shfl_add2(ps1, 2);
            ps0 = shfl_add2(ps0, 4); ps1 = shfl_add2(ps1, 4);
            float s0, s1, s2, s3;
            upk2(ps0, s0, s1); upk2(ps1, s2, s3);
            const uint64_t rs0 = pk2(frcp(s0), frcp(s1));
            const uint64_t rs1 = pk2(frcp(s2), frcp(s3));
            #pragma unroll
            for (int n = 0; n < 2; n++) {
                const uint64_t a0 = mul2(pk2(e[n][0], e[n][1]), rs0);
                const uint64_t a1 = mul2(pk2(e[n][2], e[n][3]), rs1);
                sts128p(a_at + ((og + 8 * n) * 20u + sg * 4u) * 4u, a0, a1);
            }
        }
        __syncwarp();   // S4

        // ===== phase 5: context = attn @ v (lane owns 4s x 4d) =====
        uint64_t cx[4][2];
        #pragma unroll
        for (int m = 0; m < 4; m++) { cx[m][0] = 0ull; cx[m][1] = 0ull; }
        #pragma unroll 4
        for (int t = 0; t < S; t++) {
            uint64_t a0, a1;
            lds128p(a0, a1, a_at + t * 80u + sg * 16u);
            float4 v4;
            lds128f(v4, a_vs + (t * 36u + og * 4u) * 4u);
            const float* vv = (const float*)&v4;
            #pragma unroll
            for (int m = 0; m < 4; m++) {
                const uint64_t v2 = dup2(vv[m]);
                cx[m][0] = fma2(a0, v2, cx[m][0]);
                cx[m][1] = fma2(a1, v2, cx[m][1]);
            }
        }
        #pragma unroll
        for (int m = 0; m < 4; m++)
            sts128p(a_ct + ((og + 8 * m) * 20u + sg * 4u) * 4u, cx[m][0], cx[m][1]);
        __syncwarp();   // S5

        // ===== phase 6: O projection + residual 1 =====
        uint64_t ya[4][2];
        #pragma unroll
        for (int m = 0; m < 4; m++) { ya[m][0] = bod[m]; ya[m][1] = bod[m]; }
        #pragma unroll 4
        for (int j = 0; j < D; j++) {
            uint64_t c0, c1;
            lds128p(c0, c1, a_ct + j * 80u + sg * 16u);
            float4 wo4;
            lds128f(wo4, w_o + j * 128u + og * 16u);
            const float* o4 = (const float*)&wo4;
            #pragma unroll
            for (int m = 0; m < 4; m++) {
                const uint64_t w2v = dup2(o4[m]);
                ya[m][0] = fma2(c0, w2v, ya[m][0]);
                ya[m][1] = fma2(c1, w2v, ya[m][1]);
            }
        }
        // residual: x tile re-read from xT
        #pragma unroll
        for (int m = 0; m < 4; m++) {
            uint64_t x0, x1;
            lds128p(x0, x1, a_xt + ((og + 8 * m) * 20u + sg * 4u) * 4u);
            ya[m][0] = add2(ya[m][0], x0);
            ya[m][1] = add2(ya[m][1], x1);
        }
        #pragma unroll
        for (int m = 0; m < 4; m++)
            sts128p(a_yt + ((og + 8 * m) * 20u + sg * 4u) * 4u, ya[m][0], ya[m][1]);
        __syncwarp();   // S6

        // ===== phase 7: FFN1 + ReLU (lane owns 4s x 8f) =====
        uint64_t ha[8][2];
        #pragma unroll
        for (int m = 0; m < 8; m++) { ha[m][0] = b1d[m]; ha[m][1] = b1d[m]; }
        #pragma unroll 4
        for (int j = 0; j < D; j++) {
            uint64_t y0, y1;
            lds128p(y0, y1, a_yt + j * 80u + sg * 16u);
            float4 wa4, wb4;
            lds128f(wa4, w_1a + j * 128u + og * 16u);
            lds128f(wb4, w_1b + j * 128u + og * 16u);
            const float* wa = (const float*)&wa4;
            const float* wb = (const float*)&wb4;
            #pragma unroll
            for (int m = 0; m < 4; m++) {
                const uint64_t w2a = dup2(wa[m]), w2b = dup2(wb[m]);
                ha[m][0]     = fma2(y0, w2a, ha[m][0]);
                ha[m][1]     = fma2(y1, w2a, ha[m][1]);
                ha[m + 4][0] = fma2(y0, w2b, ha[m + 4][0]);
                ha[m + 4][1] = fma2(y1, w2b, ha[m + 4][1]);
            }
        }
        #pragma unroll
        for (int m = 0; m < 8; m++) {
            float f0, f1, f2, f3;
            upk2(ha[m][0], f0, f1);
            upk2(ha[m][1], f2, f3);
            sts128p(a_ht + ((og + 8 * m) * 20u + sg * 4u) * 4u,
                    pk2(fmaxf(f0, 0.f), fmaxf(f1, 0.f)),
                    pk2(fmaxf(f2, 0.f), fmaxf(f3, 0.f)));
        }
        __syncwarp();   // S7

        // ===== phase 8: FFN2 + residual 2 -> global =====
        uint64_t za[4][2];
        #pragma unroll
        for (int m = 0; m < 4; m++) { za[m][0] = b2d[m]; za[m][1] = b2d[m]; }
        #pragma unroll 4
        for (int f = 0; f < FFNH; f++) {
            uint64_t h0, h1;
            lds128p(h0, h1, a_ht + f * 80u + sg * 16u);
            float4 w24;
            lds128f(w24, w_2 + f * 128u + og * 16u);
            const float* w4 = (const float*)&w24;
            #pragma unroll
            for (int m = 0; m < 4; m++) {
                const uint64_t w2v = dup2(w4[m]);
                za[m][0] = fma2(h0, w2v, za[m][0]);
                za[m][1] = fma2(h1, w2v, za[m][1]);
            }
        }
        float* ob = Out + (size_t)b * (S * D);
        #pragma unroll
        for (int m = 0; m < 4; m++) {
            #pragma unroll
            for (int p = 0; p < 2; p++) {
                const uint64_t z2 = add2(za[m][p], ya[m][p]);
                float z0, z1;
                upk2(z2, z0, z1);
                const int s0 = 4 * sg + 2 * p;
                ob[s0 * D + og + 8 * m]       = z0;
                ob[(s0 + 1) * D + og + 8 * m] = z1;
            }
        }
        __syncwarp();   // order hT reads before next batch's stores
    }
}

extern "C" void kernel_launch(void* const* d_in, const int* in_sizes, int n_in,
                              void* d_out, int out_size) {
    const float* X  = (const float*)d_in[0];
    const float* Wq = (const float*)d_in[1];
    const float* bq = (const float*)d_in[2];
    const float* Wk = (const float*)d_in[3];
    const float* bk = (const float*)d_in[4];
    const float* Wv = (const float*)d_in[5];
    const float* bv = (const float*)d_in[6];
    const float* Wo = (const float*)d_in[7];
    const float* bo = (const float*)d_in[8];
    const float* W1 = (const float*)d_in[9];
    const float* b1 = (const float*)d_in[10];
    const float* W2 = (const float*)d_in[11];
    const float* b2 = (const float*)d_in[12];
    float* Out = (float*)d_out;

    const int B = in_sizes[0] / (S * D);

    cudaFuncSetAttribute(tinyformer_kernel,
                         cudaFuncAttributeMaxDynamicSharedMemorySize, SMEM_BYTES);

    int blocks = 148;
    int max_blocks = (B + WARPS - 1) / WARPS;
    if (blocks > max_blocks) blocks = max_blocks;

    tinyformer_kernel<<<blocks, THREADS, SMEM_BYTES>>>(
        X, Wq, bq, Wk, bk, Wv, bv, Wo, bo, W1, b1, W2, b2, Out, B);
}